// round 15
// baseline (speedup 1.0000x reference)
#include <cuda_runtime.h>
#include <cuda_bf16.h>
#include <cstdint>
#include <math.h>

#define NMAX 100000
#define EMAX 1600000
#define IN_F 128
#define HID_F 128
#define OUT_F 64

// ---------------- scratch (static device globals; no allocation) ----------------
// zero-initialized trio packed together so one cudaMemsetAsync clears all three
__device__ int   g_zeroed[3 * NMAX];   // [out_deg | in_deg | cursor]
#define G_OUT_DEG (g_zeroed)
#define G_IN_DEG  (g_zeroed + NMAX)
#define G_CURSOR  (g_zeroed + 2 * NMAX)

__device__ float g_out_norm[NMAX];
__device__ float g_in_norm[NMAX];
__device__ int   g_row_off[NMAX];          // exclusive prefix of in_deg (per-block partial)
__device__ int   g_csr_src[EMAX];
__device__ __nv_bfloat162 g_featb[(size_t)NMAX * 64];  // feat * out_norm, bf16 (128 vals/row)
__device__ float g_agg1[(size_t)NMAX * IN_F];
__device__ float g_h1[(size_t)NMAX * HID_F];
__device__ __nv_bfloat162 g_zb[(size_t)NMAX * 32];     // z, bf16 (64 vals/row)
__device__ __nv_bfloat162 g_embb[(size_t)NMAX * 32];   // emb, bf16 (64 vals/row)
__device__ int   g_bsum[256];

// ---------------- helpers ----------------
__device__ __forceinline__ uint32_t f2tf32(float x) {
    uint32_t r;
    asm("cvt.rna.tf32.f32 %0, %1;" : "=r"(r) : "f"(x));
    return r;
}

__device__ __forceinline__ void mma_tf32(float& d0, float& d1, float& d2, float& d3,
                                         uint32_t a0, uint32_t a1, uint32_t a2, uint32_t a3,
                                         uint32_t b0, uint32_t b1) {
    asm volatile(
        "mma.sync.aligned.m16n8k8.row.col.f32.tf32.tf32.f32 "
        "{%0,%1,%2,%3}, {%4,%5,%6,%7}, {%8,%9}, {%0,%1,%2,%3};\n"
        : "+f"(d0), "+f"(d1), "+f"(d2), "+f"(d3)
        : "r"(a0), "r"(a1), "r"(a2), "r"(a3), "r"(b0), "r"(b1));
}

// ---------------- setup kernels ----------------
__global__ void k_deg(const int* __restrict__ es, const int* __restrict__ ed, int E) {
    int i = blockIdx.x * blockDim.x + threadIdx.x;
    if (i < E) {
        atomicAdd(&G_OUT_DEG[es[i]], 1);
        atomicAdd(&G_IN_DEG[ed[i]], 1);
    }
}

// scan of in_deg -> row_off (per-block exclusive), block sums -> g_bsum. Fused norms.
__global__ void k_scan1(int n) {
    __shared__ int s[1024];
    int t = threadIdx.x;
    int i = blockIdx.x * 1024 + t;
    int v = (i < n) ? G_IN_DEG[i] : 0;
    if (i < n) {
        g_in_norm[i]  = rsqrtf(fmaxf((float)v, 1.0f));
        g_out_norm[i] = rsqrtf(fmaxf((float)G_OUT_DEG[i], 1.0f));
    }
    s[t] = v;
    __syncthreads();
    for (int off = 1; off < 1024; off <<= 1) {
        int x = (t >= off) ? s[t - off] : 0;
        __syncthreads();
        s[t] += x;
        __syncthreads();
    }
    if (i < n) g_row_off[i] = s[t] - v;   // exclusive within block
    if (t == 1023) g_bsum[blockIdx.x] = s[t];
}

__global__ void k_scan2(int nb) {
    __shared__ int s[256];
    int t = threadIdx.x;
    int v = (t < nb) ? g_bsum[t] : 0;
    s[t] = v;
    __syncthreads();
    for (int off = 1; off < 256; off <<= 1) {
        int x = (t >= off) ? s[t - off] : 0;
        __syncthreads();
        s[t] += x;
        __syncthreads();
    }
    if (t < nb) g_bsum[t] = s[t] - v;     // exclusive
}

// Fused: blocks [0, nbFill) scatter edges into CSR; blocks [nbFill, nbFill+nbPrep)
// build featb = bf16(feat * out_norm). Both depend only on scan results.
__global__ void k_fill_prep(const int* __restrict__ es, const int* __restrict__ ed, int E,
                            const float* __restrict__ feat, int n, int nbFill) {
    if ((int)blockIdx.x < nbFill) {
        int i = blockIdx.x * blockDim.x + threadIdx.x;
        if (i < E) {
            int d = ed[i];
            int p = atomicAdd(&G_CURSOR[d], 1);
            g_csr_src[g_row_off[d] + g_bsum[d >> 10] + p] = es[i];
        }
    } else {
        int i = (blockIdx.x - nbFill) * blockDim.x + threadIdx.x;
        if (i >= n * 32) return;
        int row = i >> 5;
        int c = i & 31;
        float w = g_out_norm[row];
        float4 v = *reinterpret_cast<const float4*>(feat + (size_t)row * 128 + c * 4);
        g_featb[(size_t)row * 64 + c * 2 + 0] = __floats2bfloat162_rn(v.x * w, v.y * w);
        g_featb[(size_t)row * 64 + c * 2 + 1] = __floats2bfloat162_rn(v.z * w, v.w * w);
    }
}

// ---------------- aggregation 1: warp per node, coalesced idx preload + shfl ----
__global__ void k_agg1(int n) {
    int warp = (blockIdx.x * blockDim.x + threadIdx.x) >> 5;
    int lane = threadIdx.x & 31;
    if (warp >= n) return;
    int start = g_row_off[warp] + g_bsum[warp >> 10];
    int deg   = G_IN_DEG[warp];
    float4 acc = make_float4(0.f, 0.f, 0.f, 0.f);
    for (int base = 0; base < deg; base += 32) {
        int cnt = deg - base;
        if (cnt > 32) cnt = 32;
        int idx = 0;
        if (lane < cnt) idx = g_csr_src[start + base + lane];   // one coalesced load
        #pragma unroll 4
        for (int j = 0; j < cnt; j++) {
            int s = __shfl_sync(0xffffffffu, idx, j);
            uint2 u = *reinterpret_cast<const uint2*>(g_featb + (size_t)s * 64 + lane * 2);
            float2 f0 = __bfloat1622float2(*reinterpret_cast<__nv_bfloat162*>(&u.x));
            float2 f1 = __bfloat1622float2(*reinterpret_cast<__nv_bfloat162*>(&u.y));
            acc.x += f0.x; acc.y += f0.y; acc.z += f1.x; acc.w += f1.y;
        }
    }
    *reinterpret_cast<float4*>(g_agg1 + (size_t)warp * IN_F + lane * 4) = acc;
}

// ---------------- GEMM1 (tf32 tensor cores): h1 = relu((agg1 @ W1) * in_norm + b1)
// Block tile 128x128, K chunked by 32. 256 threads = 8 warps, warp tile 32x64.
__global__ void k_gemm1(const float* __restrict__ W1, const float* __restrict__ b1, int n) {
    __shared__ float As[128][33];
    __shared__ float Bs[128][33];
    int tid = threadIdx.x;
    int lane = tid & 31;
    int wid = tid >> 5;
    int warpM = wid & 3;
    int warpN = wid >> 2;
    int rowBase = blockIdx.x * 128;

    float acc[2][8][4];
    #pragma unroll
    for (int mi = 0; mi < 2; mi++)
        #pragma unroll
        for (int ni = 0; ni < 8; ni++)
            #pragma unroll
            for (int r = 0; r < 4; r++) acc[mi][ni][r] = 0.f;

    int ar  = tid >> 1;
    int ac0 = (tid & 1) * 16;
    int bk  = tid >> 3;
    int bn0 = (tid & 7) * 16;

    for (int k0 = 0; k0 < 128; k0 += 32) {
        {
            int gr = rowBase + ar;
            if (gr < n) {
                const float4* ap = reinterpret_cast<const float4*>(g_agg1 + (size_t)gr * 128 + k0 + ac0);
                #pragma unroll
                for (int j = 0; j < 4; j++) {
                    float4 v = ap[j];
                    As[ar][ac0 + j * 4 + 0] = __uint_as_float(f2tf32(v.x));
                    As[ar][ac0 + j * 4 + 1] = __uint_as_float(f2tf32(v.y));
                    As[ar][ac0 + j * 4 + 2] = __uint_as_float(f2tf32(v.z));
                    As[ar][ac0 + j * 4 + 3] = __uint_as_float(f2tf32(v.w));
                }
            } else {
                #pragma unroll
                for (int j = 0; j < 16; j++) As[ar][ac0 + j] = 0.f;
            }
        }
        {
            const float4* bp = reinterpret_cast<const float4*>(W1 + (size_t)(k0 + bk) * 128 + bn0);
            #pragma unroll
            for (int j = 0; j < 4; j++) {
                float4 v = bp[j];
                Bs[bn0 + j * 4 + 0][bk] = __uint_as_float(f2tf32(v.x));
                Bs[bn0 + j * 4 + 1][bk] = __uint_as_float(f2tf32(v.y));
                Bs[bn0 + j * 4 + 2][bk] = __uint_as_float(f2tf32(v.z));
                Bs[bn0 + j * 4 + 3][bk] = __uint_as_float(f2tf32(v.w));
            }
        }
        __syncthreads();

        int g = lane >> 2, c = lane & 3;
        #pragma unroll
        for (int kk = 0; kk < 4; kk++) {
            int kb = kk * 8;
            uint32_t a[2][4];
            #pragma unroll
            for (int mi = 0; mi < 2; mi++) {
                int r = warpM * 32 + mi * 16 + g;
                a[mi][0] = __float_as_uint(As[r][kb + c]);
                a[mi][1] = __float_as_uint(As[r + 8][kb + c]);
                a[mi][2] = __float_as_uint(As[r][kb + c + 4]);
                a[mi][3] = __float_as_uint(As[r + 8][kb + c + 4]);
            }
            #pragma unroll
            for (int ni = 0; ni < 8; ni++) {
                int col = warpN * 64 + ni * 8 + g;
                uint32_t b0 = __float_as_uint(Bs[col][kb + c]);
                uint32_t b1v = __float_as_uint(Bs[col][kb + c + 4]);
                #pragma unroll
                for (int mi = 0; mi < 2; mi++)
                    mma_tf32(acc[mi][ni][0], acc[mi][ni][1], acc[mi][ni][2], acc[mi][ni][3],
                             a[mi][0], a[mi][1], a[mi][2], a[mi][3], b0, b1v);
            }
        }
        __syncthreads();
    }

    int g = lane >> 2, c = lane & 3;
    #pragma unroll
    for (int mi = 0; mi < 2; mi++) {
        int r0 = rowBase + warpM * 32 + mi * 16 + g;
        int r1 = r0 + 8;
        float inn0 = (r0 < n) ? g_in_norm[r0] : 0.f;
        float inn1 = (r1 < n) ? g_in_norm[r1] : 0.f;
        #pragma unroll
        for (int ni = 0; ni < 8; ni++) {
            int col = warpN * 64 + ni * 8 + 2 * c;
            float bb0 = b1[col], bb1 = b1[col + 1];
            if (r0 < n) {
                float2 o;
                o.x = fmaxf(acc[mi][ni][0] * inn0 + bb0, 0.f);
                o.y = fmaxf(acc[mi][ni][1] * inn0 + bb1, 0.f);
                *reinterpret_cast<float2*>(g_h1 + (size_t)r0 * 128 + col) = o;
            }
            if (r1 < n) {
                float2 o;
                o.x = fmaxf(acc[mi][ni][2] * inn1 + bb0, 0.f);
                o.y = fmaxf(acc[mi][ni][3] * inn1 + bb1, 0.f);
                *reinterpret_cast<float2*>(g_h1 + (size_t)r1 * 128 + col) = o;
            }
        }
    }
}

// ---------------- GEMM2 (tf32): z = (h1 * out_norm) @ W2, output bf16 ----------------
// Block tile 128x64. 256 threads = 8 warps, warp tile 32x32 (warps 4x2).
__global__ void k_gemm2(const float* __restrict__ W2, int n) {
    __shared__ float As[128][33];
    __shared__ float Bs[64][33];
    int tid = threadIdx.x;
    int lane = tid & 31;
    int wid = tid >> 5;
    int warpM = wid & 3;
    int warpN = wid >> 2;
    int rowBase = blockIdx.x * 128;

    float acc[2][4][4];
    #pragma unroll
    for (int mi = 0; mi < 2; mi++)
        #pragma unroll
        for (int ni = 0; ni < 4; ni++)
            #pragma unroll
            for (int r = 0; r < 4; r++) acc[mi][ni][r] = 0.f;

    int ar  = tid >> 1;
    int ac0 = (tid & 1) * 16;
    int bk  = tid >> 3;
    int bn0 = (tid & 7) * 8;

    for (int k0 = 0; k0 < 128; k0 += 32) {
        {
            int gr = rowBase + ar;
            if (gr < n) {
                float w = g_out_norm[gr];
                const float4* ap = reinterpret_cast<const float4*>(g_h1 + (size_t)gr * 128 + k0 + ac0);
                #pragma unroll
                for (int j = 0; j < 4; j++) {
                    float4 v = ap[j];
                    As[ar][ac0 + j * 4 + 0] = __uint_as_float(f2tf32(v.x * w));
                    As[ar][ac0 + j * 4 + 1] = __uint_as_float(f2tf32(v.y * w));
                    As[ar][ac0 + j * 4 + 2] = __uint_as_float(f2tf32(v.z * w));
                    As[ar][ac0 + j * 4 + 3] = __uint_as_float(f2tf32(v.w * w));
                }
            } else {
                #pragma unroll
                for (int j = 0; j < 16; j++) As[ar][ac0 + j] = 0.f;
            }
        }
        {
            const float4* bp = reinterpret_cast<const float4*>(W2 + (size_t)(k0 + bk) * 64 + bn0);
            #pragma unroll
            for (int j = 0; j < 2; j++) {
                float4 v = bp[j];
                Bs[bn0 + j * 4 + 0][bk] = __uint_as_float(f2tf32(v.x));
                Bs[bn0 + j * 4 + 1][bk] = __uint_as_float(f2tf32(v.y));
                Bs[bn0 + j * 4 + 2][bk] = __uint_as_float(f2tf32(v.z));
                Bs[bn0 + j * 4 + 3][bk] = __uint_as_float(f2tf32(v.w));
            }
        }
        __syncthreads();

        int g = lane >> 2, c = lane & 3;
        #pragma unroll
        for (int kk = 0; kk < 4; kk++) {
            int kb = kk * 8;
            uint32_t a[2][4];
            #pragma unroll
            for (int mi = 0; mi < 2; mi++) {
                int r = warpM * 32 + mi * 16 + g;
                a[mi][0] = __float_as_uint(As[r][kb + c]);
                a[mi][1] = __float_as_uint(As[r + 8][kb + c]);
                a[mi][2] = __float_as_uint(As[r][kb + c + 4]);
                a[mi][3] = __float_as_uint(As[r + 8][kb + c + 4]);
            }
            #pragma unroll
            for (int ni = 0; ni < 4; ni++) {
                int col = warpN * 32 + ni * 8 + g;
                uint32_t b0 = __float_as_uint(Bs[col][kb + c]);
                uint32_t b1v = __float_as_uint(Bs[col][kb + c + 4]);
                #pragma unroll
                for (int mi = 0; mi < 2; mi++)
                    mma_tf32(acc[mi][ni][0], acc[mi][ni][1], acc[mi][ni][2], acc[mi][ni][3],
                             a[mi][0], a[mi][1], a[mi][2], a[mi][3], b0, b1v);
            }
        }
        __syncthreads();
    }

    int g = lane >> 2, c = lane & 3;
    #pragma unroll
    for (int mi = 0; mi < 2; mi++) {
        int r0 = rowBase + warpM * 32 + mi * 16 + g;
        int r1 = r0 + 8;
        #pragma unroll
        for (int ni = 0; ni < 4; ni++) {
            int col = warpN * 32 + ni * 8 + 2 * c;
            if (r0 < n)
                g_zb[(size_t)r0 * 32 + (col >> 1)] = __floats2bfloat162_rn(acc[mi][ni][0], acc[mi][ni][1]);
            if (r1 < n)
                g_zb[(size_t)r1 * 32 + (col >> 1)] = __floats2bfloat162_rn(acc[mi][ni][2], acc[mi][ni][3]);
        }
    }
}

// ---------------- aggregation 2: warp per node, coalesced idx preload + shfl ----
__global__ void k_agg2(const float* __restrict__ b2, int n) {
    int warp = (blockIdx.x * blockDim.x + threadIdx.x) >> 5;
    int lane = threadIdx.x & 31;
    if (warp >= n) return;
    int start = g_row_off[warp] + g_bsum[warp >> 10];
    int deg   = G_IN_DEG[warp];
    float2 acc = make_float2(0.f, 0.f);
    for (int base = 0; base < deg; base += 32) {
        int cnt = deg - base;
        if (cnt > 32) cnt = 32;
        int idx = 0;
        if (lane < cnt) idx = g_csr_src[start + base + lane];   // one coalesced load
        #pragma unroll 4
        for (int j = 0; j < cnt; j++) {
            int s = __shfl_sync(0xffffffffu, idx, j);
            float2 v = __bfloat1622float2(g_zb[(size_t)s * 32 + lane]);
            acc.x += v.x; acc.y += v.y;
        }
    }
    float inn = g_in_norm[warp];
    float ox = acc.x * inn + b2[lane * 2 + 0];
    float oy = acc.y * inn + b2[lane * 2 + 1];
    g_embb[(size_t)warp * 32 + lane] = __floats2bfloat162_rn(ox, oy);
}

// ---------------- scoring: 4 threads per query, bf16 emb ----------------
__global__ void k_score(const int* __restrict__ qs, const int* __restrict__ qd,
                        float* __restrict__ out, int Q) {
    int gt = blockIdx.x * blockDim.x + threadIdx.x;
    int q = gt >> 2;
    int l = gt & 3;
    if (q >= Q) return;
    int s = qs[q], d = qd[q];
    const uint4* ap = reinterpret_cast<const uint4*>(g_embb + (size_t)s * 32) + l * 2;
    const uint4* bp = reinterpret_cast<const uint4*>(g_embb + (size_t)d * 32) + l * 2;
    float dot = 0.f;
    #pragma unroll
    for (int j = 0; j < 2; j++) {
        uint4 ua = ap[j], ub = bp[j];
        const uint32_t* pa = &ua.x;
        const uint32_t* pb = &ub.x;
        #pragma unroll
        for (int k = 0; k < 4; k++) {
            float2 fa = __bfloat1622float2(*reinterpret_cast<const __nv_bfloat162*>(&pa[k]));
            float2 fb = __bfloat1622float2(*reinterpret_cast<const __nv_bfloat162*>(&pb[k]));
            dot += fa.x * fb.x + fa.y * fb.y;
        }
    }
    dot += __shfl_down_sync(0xffffffff, dot, 2, 4);
    dot += __shfl_down_sync(0xffffffff, dot, 1, 4);
    if (l == 0) out[q] = 1.0f / (1.0f + __expf(-dot));
}

// ---------------- launch ----------------
extern "C" void kernel_launch(void* const* d_in, const int* in_sizes, int n_in,
                              void* d_out, int out_size) {
    const float* feat = (const float*)d_in[0];
    const int*   es   = (const int*)d_in[1];
    const int*   ed   = (const int*)d_in[2];
    const int*   qs   = (const int*)d_in[3];
    const int*   qd   = (const int*)d_in[4];
    const float* W1   = (const float*)d_in[5];
    const float* b1   = (const float*)d_in[6];
    const float* W2   = (const float*)d_in[7];
    const float* b2   = (const float*)d_in[8];
    float* out = (float*)d_out;

    int N = in_sizes[0] / IN_F;
    int E = in_sizes[1];
    int Q = in_sizes[3];

    int nb256E = (E + 255) / 256;
    int nbScan = (N + 1023) / 1024;
    int nbPrep = (N * 32 + 255) / 256;

    // zero out_deg/in_deg/cursor in one memset (graph-capturable, no alloc)
    void* zp = nullptr;
    cudaGetSymbolAddress(&zp, g_zeroed);
    cudaMemsetAsync(zp, 0, sizeof(int) * 3 * NMAX);

    k_deg<<<nb256E, 256>>>(es, ed, E);
    k_scan1<<<nbScan, 1024>>>(N);
    k_scan2<<<1, 256>>>(nbScan);
    k_fill_prep<<<nb256E + nbPrep, 256>>>(es, ed, E, feat, N, nb256E);

    k_agg1<<<(N + 7) / 8, 256>>>(N);
    k_gemm1<<<(N + 127) / 128, 256>>>(W1, b1, N);
    k_gemm2<<<(N + 127) / 128, 256>>>(W2, N);
    k_agg2<<<(N + 7) / 8, 256>>>(b2, N);
    k_score<<<((size_t)Q * 4 + 255) / 256, 256>>>(qs, qd, out, Q);
}

// round 16
// speedup vs baseline: 1.0450x; 1.0450x over previous
#include <cuda_runtime.h>
#include <cuda_bf16.h>
#include <cstdint>
#include <math.h>

#define NMAX 100000
#define EMAX 1600000
#define IN_F 128
#define HID_F 128
#define OUT_F 64

// ---------------- scratch (static device globals; no allocation) ----------------
// zero-initialized trio packed together so one cudaMemsetAsync clears all three
__device__ int   g_zeroed[3 * NMAX];   // [out_deg | in_deg | cursor]
#define G_OUT_DEG (g_zeroed)
#define G_IN_DEG  (g_zeroed + NMAX)
#define G_CURSOR  (g_zeroed + 2 * NMAX)

__device__ float g_out_norm[NMAX];
__device__ float g_in_norm[NMAX];
__device__ int   g_row_off[NMAX];          // exclusive prefix of in_deg (per-block partial)
__device__ int   g_csr_src[EMAX];
__device__ __nv_bfloat162 g_featb[(size_t)NMAX * 64];  // feat * out_norm, bf16 (128 vals/row)
__device__ float g_agg1[(size_t)NMAX * IN_F];
__device__ float g_h1[(size_t)NMAX * HID_F];
__device__ __nv_bfloat162 g_zb[(size_t)NMAX * 32];     // z, bf16 (64 vals/row)
__device__ __nv_bfloat162 g_embb[(size_t)NMAX * 32];   // emb, bf16 (64 vals/row)
__device__ int   g_bsum[256];

// ---------------- helpers ----------------
__device__ __forceinline__ uint32_t f2tf32(float x) {
    uint32_t r;
    asm("cvt.rna.tf32.f32 %0, %1;" : "=r"(r) : "f"(x));
    return r;
}

__device__ __forceinline__ void mma_tf32(float& d0, float& d1, float& d2, float& d3,
                                         uint32_t a0, uint32_t a1, uint32_t a2, uint32_t a3,
                                         uint32_t b0, uint32_t b1) {
    asm volatile(
        "mma.sync.aligned.m16n8k8.row.col.f32.tf32.tf32.f32 "
        "{%0,%1,%2,%3}, {%4,%5,%6,%7}, {%8,%9}, {%0,%1,%2,%3};\n"
        : "+f"(d0), "+f"(d1), "+f"(d2), "+f"(d3)
        : "r"(a0), "r"(a1), "r"(a2), "r"(a3), "r"(b0), "r"(b1));
}

// ---------------- setup kernels ----------------
__global__ void k_deg(const int* __restrict__ es, const int* __restrict__ ed, int E) {
    int i = blockIdx.x * blockDim.x + threadIdx.x;
    if (i < E) {
        atomicAdd(&G_OUT_DEG[es[i]], 1);
        atomicAdd(&G_IN_DEG[ed[i]], 1);
    }
}

// scan of in_deg -> row_off (per-block exclusive), block sums -> g_bsum. Fused norms.
__global__ void k_scan1(int n) {
    __shared__ int s[1024];
    int t = threadIdx.x;
    int i = blockIdx.x * 1024 + t;
    int v = (i < n) ? G_IN_DEG[i] : 0;
    if (i < n) {
        g_in_norm[i]  = rsqrtf(fmaxf((float)v, 1.0f));
        g_out_norm[i] = rsqrtf(fmaxf((float)G_OUT_DEG[i], 1.0f));
    }
    s[t] = v;
    __syncthreads();
    for (int off = 1; off < 1024; off <<= 1) {
        int x = (t >= off) ? s[t - off] : 0;
        __syncthreads();
        s[t] += x;
        __syncthreads();
    }
    if (i < n) g_row_off[i] = s[t] - v;   // exclusive within block
    if (t == 1023) g_bsum[blockIdx.x] = s[t];
}

__global__ void k_scan2(int nb) {
    __shared__ int s[256];
    int t = threadIdx.x;
    int v = (t < nb) ? g_bsum[t] : 0;
    s[t] = v;
    __syncthreads();
    for (int off = 1; off < 256; off <<= 1) {
        int x = (t >= off) ? s[t - off] : 0;
        __syncthreads();
        s[t] += x;
        __syncthreads();
    }
    if (t < nb) g_bsum[t] = s[t] - v;     // exclusive
}

// Fused: blocks [0, nbFill) scatter edges into CSR; blocks [nbFill, nbFill+nbPrep)
// build featb = bf16(feat * out_norm). Both depend only on scan results.
__global__ void k_fill_prep(const int* __restrict__ es, const int* __restrict__ ed, int E,
                            const float* __restrict__ feat, int n, int nbFill) {
    if ((int)blockIdx.x < nbFill) {
        int i = blockIdx.x * blockDim.x + threadIdx.x;
        if (i < E) {
            int d = ed[i];
            int p = atomicAdd(&G_CURSOR[d], 1);
            g_csr_src[g_row_off[d] + g_bsum[d >> 10] + p] = es[i];
        }
    } else {
        int i = (blockIdx.x - nbFill) * blockDim.x + threadIdx.x;
        if (i >= n * 32) return;
        int row = i >> 5;
        int c = i & 31;
        float w = g_out_norm[row];
        float4 v = *reinterpret_cast<const float4*>(feat + (size_t)row * 128 + c * 4);
        g_featb[(size_t)row * 64 + c * 2 + 0] = __floats2bfloat162_rn(v.x * w, v.y * w);
        g_featb[(size_t)row * 64 + c * 2 + 1] = __floats2bfloat162_rn(v.z * w, v.w * w);
    }
}

// ---------------- aggregation 1: warp per node, 128 bf16 (256B/edge) ----------------
__global__ void k_agg1(int n) {
    int warp = (blockIdx.x * blockDim.x + threadIdx.x) >> 5;
    int lane = threadIdx.x & 31;
    if (warp >= n) return;
    int start = g_row_off[warp] + g_bsum[warp >> 10];
    int deg   = G_IN_DEG[warp];
    float4 acc = make_float4(0.f, 0.f, 0.f, 0.f);
    #pragma unroll 4
    for (int e = 0; e < deg; e++) {
        int s = g_csr_src[start + e];
        uint2 u = *reinterpret_cast<const uint2*>(g_featb + (size_t)s * 64 + lane * 2);
        float2 f0 = __bfloat1622float2(*reinterpret_cast<__nv_bfloat162*>(&u.x));
        float2 f1 = __bfloat1622float2(*reinterpret_cast<__nv_bfloat162*>(&u.y));
        acc.x += f0.x; acc.y += f0.y; acc.z += f1.x; acc.w += f1.y;
    }
    *reinterpret_cast<float4*>(g_agg1 + (size_t)warp * IN_F + lane * 4) = acc;
}

// ---------------- GEMM1 (tf32 tensor cores): h1 = relu((agg1 @ W1) * in_norm + b1)
// Block tile 128x128, K chunked by 32. 256 threads = 8 warps, warp tile 32x64.
__global__ void k_gemm1(const float* __restrict__ W1, const float* __restrict__ b1, int n) {
    __shared__ float As[128][33];
    __shared__ float Bs[128][33];
    int tid = threadIdx.x;
    int lane = tid & 31;
    int wid = tid >> 5;
    int warpM = wid & 3;
    int warpN = wid >> 2;
    int rowBase = blockIdx.x * 128;

    float acc[2][8][4];
    #pragma unroll
    for (int mi = 0; mi < 2; mi++)
        #pragma unroll
        for (int ni = 0; ni < 8; ni++)
            #pragma unroll
            for (int r = 0; r < 4; r++) acc[mi][ni][r] = 0.f;

    int ar  = tid >> 1;
    int ac0 = (tid & 1) * 16;
    int bk  = tid >> 3;
    int bn0 = (tid & 7) * 16;

    for (int k0 = 0; k0 < 128; k0 += 32) {
        {
            int gr = rowBase + ar;
            if (gr < n) {
                const float4* ap = reinterpret_cast<const float4*>(g_agg1 + (size_t)gr * 128 + k0 + ac0);
                #pragma unroll
                for (int j = 0; j < 4; j++) {
                    float4 v = ap[j];
                    As[ar][ac0 + j * 4 + 0] = __uint_as_float(f2tf32(v.x));
                    As[ar][ac0 + j * 4 + 1] = __uint_as_float(f2tf32(v.y));
                    As[ar][ac0 + j * 4 + 2] = __uint_as_float(f2tf32(v.z));
                    As[ar][ac0 + j * 4 + 3] = __uint_as_float(f2tf32(v.w));
                }
            } else {
                #pragma unroll
                for (int j = 0; j < 16; j++) As[ar][ac0 + j] = 0.f;
            }
        }
        {
            const float4* bp = reinterpret_cast<const float4*>(W1 + (size_t)(k0 + bk) * 128 + bn0);
            #pragma unroll
            for (int j = 0; j < 4; j++) {
                float4 v = bp[j];
                Bs[bn0 + j * 4 + 0][bk] = __uint_as_float(f2tf32(v.x));
                Bs[bn0 + j * 4 + 1][bk] = __uint_as_float(f2tf32(v.y));
                Bs[bn0 + j * 4 + 2][bk] = __uint_as_float(f2tf32(v.z));
                Bs[bn0 + j * 4 + 3][bk] = __uint_as_float(f2tf32(v.w));
            }
        }
        __syncthreads();

        int g = lane >> 2, c = lane & 3;
        #pragma unroll
        for (int kk = 0; kk < 4; kk++) {
            int kb = kk * 8;
            uint32_t a[2][4];
            #pragma unroll
            for (int mi = 0; mi < 2; mi++) {
                int r = warpM * 32 + mi * 16 + g;
                a[mi][0] = __float_as_uint(As[r][kb + c]);
                a[mi][1] = __float_as_uint(As[r + 8][kb + c]);
                a[mi][2] = __float_as_uint(As[r][kb + c + 4]);
                a[mi][3] = __float_as_uint(As[r + 8][kb + c + 4]);
            }
            #pragma unroll
            for (int ni = 0; ni < 8; ni++) {
                int col = warpN * 64 + ni * 8 + g;
                uint32_t b0 = __float_as_uint(Bs[col][kb + c]);
                uint32_t b1v = __float_as_uint(Bs[col][kb + c + 4]);
                #pragma unroll
                for (int mi = 0; mi < 2; mi++)
                    mma_tf32(acc[mi][ni][0], acc[mi][ni][1], acc[mi][ni][2], acc[mi][ni][3],
                             a[mi][0], a[mi][1], a[mi][2], a[mi][3], b0, b1v);
            }
        }
        __syncthreads();
    }

    int g = lane >> 2, c = lane & 3;
    #pragma unroll
    for (int mi = 0; mi < 2; mi++) {
        int r0 = rowBase + warpM * 32 + mi * 16 + g;
        int r1 = r0 + 8;
        float inn0 = (r0 < n) ? g_in_norm[r0] : 0.f;
        float inn1 = (r1 < n) ? g_in_norm[r1] : 0.f;
        #pragma unroll
        for (int ni = 0; ni < 8; ni++) {
            int col = warpN * 64 + ni * 8 + 2 * c;
            float bb0 = b1[col], bb1 = b1[col + 1];
            if (r0 < n) {
                float2 o;
                o.x = fmaxf(acc[mi][ni][0] * inn0 + bb0, 0.f);
                o.y = fmaxf(acc[mi][ni][1] * inn0 + bb1, 0.f);
                *reinterpret_cast<float2*>(g_h1 + (size_t)r0 * 128 + col) = o;
            }
            if (r1 < n) {
                float2 o;
                o.x = fmaxf(acc[mi][ni][2] * inn1 + bb0, 0.f);
                o.y = fmaxf(acc[mi][ni][3] * inn1 + bb1, 0.f);
                *reinterpret_cast<float2*>(g_h1 + (size_t)r1 * 128 + col) = o;
            }
        }
    }
}

// ---------------- GEMM2 (tf32): z = (h1 * out_norm) @ W2, output bf16 ----------------
// Block tile 128x64. 256 threads = 8 warps, warp tile 32x32 (warps 4x2).
__global__ void k_gemm2(const float* __restrict__ W2, int n) {
    __shared__ float As[128][33];
    __shared__ float Bs[64][33];
    int tid = threadIdx.x;
    int lane = tid & 31;
    int wid = tid >> 5;
    int warpM = wid & 3;
    int warpN = wid >> 2;
    int rowBase = blockIdx.x * 128;

    float acc[2][4][4];
    #pragma unroll
    for (int mi = 0; mi < 2; mi++)
        #pragma unroll
        for (int ni = 0; ni < 4; ni++)
            #pragma unroll
            for (int r = 0; r < 4; r++) acc[mi][ni][r] = 0.f;

    int ar  = tid >> 1;
    int ac0 = (tid & 1) * 16;
    int bk  = tid >> 3;
    int bn0 = (tid & 7) * 8;

    for (int k0 = 0; k0 < 128; k0 += 32) {
        {
            int gr = rowBase + ar;
            if (gr < n) {
                float w = g_out_norm[gr];
                const float4* ap = reinterpret_cast<const float4*>(g_h1 + (size_t)gr * 128 + k0 + ac0);
                #pragma unroll
                for (int j = 0; j < 4; j++) {
                    float4 v = ap[j];
                    As[ar][ac0 + j * 4 + 0] = __uint_as_float(f2tf32(v.x * w));
                    As[ar][ac0 + j * 4 + 1] = __uint_as_float(f2tf32(v.y * w));
                    As[ar][ac0 + j * 4 + 2] = __uint_as_float(f2tf32(v.z * w));
                    As[ar][ac0 + j * 4 + 3] = __uint_as_float(f2tf32(v.w * w));
                }
            } else {
                #pragma unroll
                for (int j = 0; j < 16; j++) As[ar][ac0 + j] = 0.f;
            }
        }
        {
            const float4* bp = reinterpret_cast<const float4*>(W2 + (size_t)(k0 + bk) * 64 + bn0);
            #pragma unroll
            for (int j = 0; j < 2; j++) {
                float4 v = bp[j];
                Bs[bn0 + j * 4 + 0][bk] = __uint_as_float(f2tf32(v.x));
                Bs[bn0 + j * 4 + 1][bk] = __uint_as_float(f2tf32(v.y));
                Bs[bn0 + j * 4 + 2][bk] = __uint_as_float(f2tf32(v.z));
                Bs[bn0 + j * 4 + 3][bk] = __uint_as_float(f2tf32(v.w));
            }
        }
        __syncthreads();

        int g = lane >> 2, c = lane & 3;
        #pragma unroll
        for (int kk = 0; kk < 4; kk++) {
            int kb = kk * 8;
            uint32_t a[2][4];
            #pragma unroll
            for (int mi = 0; mi < 2; mi++) {
                int r = warpM * 32 + mi * 16 + g;
                a[mi][0] = __float_as_uint(As[r][kb + c]);
                a[mi][1] = __float_as_uint(As[r + 8][kb + c]);
                a[mi][2] = __float_as_uint(As[r][kb + c + 4]);
                a[mi][3] = __float_as_uint(As[r + 8][kb + c + 4]);
            }
            #pragma unroll
            for (int ni = 0; ni < 4; ni++) {
                int col = warpN * 32 + ni * 8 + g;
                uint32_t b0 = __float_as_uint(Bs[col][kb + c]);
                uint32_t b1v = __float_as_uint(Bs[col][kb + c + 4]);
                #pragma unroll
                for (int mi = 0; mi < 2; mi++)
                    mma_tf32(acc[mi][ni][0], acc[mi][ni][1], acc[mi][ni][2], acc[mi][ni][3],
                             a[mi][0], a[mi][1], a[mi][2], a[mi][3], b0, b1v);
            }
        }
        __syncthreads();
    }

    int g = lane >> 2, c = lane & 3;
    #pragma unroll
    for (int mi = 0; mi < 2; mi++) {
        int r0 = rowBase + warpM * 32 + mi * 16 + g;
        int r1 = r0 + 8;
        #pragma unroll
        for (int ni = 0; ni < 4; ni++) {
            int col = warpN * 32 + ni * 8 + 2 * c;
            if (r0 < n)
                g_zb[(size_t)r0 * 32 + (col >> 1)] = __floats2bfloat162_rn(acc[mi][ni][0], acc[mi][ni][1]);
            if (r1 < n)
                g_zb[(size_t)r1 * 32 + (col >> 1)] = __floats2bfloat162_rn(acc[mi][ni][2], acc[mi][ni][3]);
        }
    }
}

// ---------------- aggregation 2: warp per node, 64 bf16 (128B/edge) ----------------
__global__ void k_agg2(const float* __restrict__ b2, int n) {
    int warp = (blockIdx.x * blockDim.x + threadIdx.x) >> 5;
    int lane = threadIdx.x & 31;
    if (warp >= n) return;
    int start = g_row_off[warp] + g_bsum[warp >> 10];
    int deg   = G_IN_DEG[warp];
    float2 acc = make_float2(0.f, 0.f);
    #pragma unroll 4
    for (int e = 0; e < deg; e++) {
        int s = g_csr_src[start + e];
        float2 v = __bfloat1622float2(g_zb[(size_t)s * 32 + lane]);
        acc.x += v.x; acc.y += v.y;
    }
    float inn = g_in_norm[warp];
    float ox = acc.x * inn + b2[lane * 2 + 0];
    float oy = acc.y * inn + b2[lane * 2 + 1];
    g_embb[(size_t)warp * 32 + lane] = __floats2bfloat162_rn(ox, oy);
}

// ---------------- scoring: 4 threads per query, bf16 emb ----------------
__global__ void k_score(const int* __restrict__ qs, const int* __restrict__ qd,
                        float* __restrict__ out, int Q) {
    int gt = blockIdx.x * blockDim.x + threadIdx.x;
    int q = gt >> 2;
    int l = gt & 3;
    if (q >= Q) return;
    int s = qs[q], d = qd[q];
    const uint4* ap = reinterpret_cast<const uint4*>(g_embb + (size_t)s * 32) + l * 2;
    const uint4* bp = reinterpret_cast<const uint4*>(g_embb + (size_t)d * 32) + l * 2;
    float dot = 0.f;
    #pragma unroll
    for (int j = 0; j < 2; j++) {
        uint4 ua = ap[j], ub = bp[j];
        const uint32_t* pa = &ua.x;
        const uint32_t* pb = &ub.x;
        #pragma unroll
        for (int k = 0; k < 4; k++) {
            float2 fa = __bfloat1622float2(*reinterpret_cast<const __nv_bfloat162*>(&pa[k]));
            float2 fb = __bfloat1622float2(*reinterpret_cast<const __nv_bfloat162*>(&pb[k]));
            dot += fa.x * fb.x + fa.y * fb.y;
        }
    }
    dot += __shfl_down_sync(0xffffffff, dot, 2, 4);
    dot += __shfl_down_sync(0xffffffff, dot, 1, 4);
    if (l == 0) out[q] = 1.0f / (1.0f + __expf(-dot));
}

// ---------------- launch ----------------
extern "C" void kernel_launch(void* const* d_in, const int* in_sizes, int n_in,
                              void* d_out, int out_size) {
    const float* feat = (const float*)d_in[0];
    const int*   es   = (const int*)d_in[1];
    const int*   ed   = (const int*)d_in[2];
    const int*   qs   = (const int*)d_in[3];
    const int*   qd   = (const int*)d_in[4];
    const float* W1   = (const float*)d_in[5];
    const float* b1   = (const float*)d_in[6];
    const float* W2   = (const float*)d_in[7];
    const float* b2   = (const float*)d_in[8];
    float* out = (float*)d_out;

    int N = in_sizes[0] / IN_F;
    int E = in_sizes[1];
    int Q = in_sizes[3];

    int nb256E = (E + 255) / 256;
    int nbScan = (N + 1023) / 1024;
    int nbPrep = (N * 32 + 255) / 256;

    // zero out_deg/in_deg/cursor in one memset (graph-capturable, no alloc)
    void* zp = nullptr;
    cudaGetSymbolAddress(&zp, g_zeroed);
    cudaMemsetAsync(zp, 0, sizeof(int) * 3 * NMAX);

    k_deg<<<nb256E, 256>>>(es, ed, E);
    k_scan1<<<nbScan, 1024>>>(N);
    k_scan2<<<1, 256>>>(nbScan);
    k_fill_prep<<<nb256E + nbPrep, 256>>>(es, ed, E, feat, N, nb256E);

    k_agg1<<<(N + 7) / 8, 256>>>(N);
    k_gemm1<<<(N + 127) / 128, 256>>>(W1, b1, N);
    k_gemm2<<<(N + 127) / 128, 256>>>(W2, N);
    k_agg2<<<(N + 7) / 8, 256>>>(b2, N);
    k_score<<<((size_t)Q * 4 + 255) / 256, 256>>>(qs, qd, out, Q);
}